// round 11
// baseline (speedup 1.0000x reference)
#include <cuda_runtime.h>
#include <cuda_fp16.h>
#include <cstdint>

static constexpr int E_EDGES = 250000;
static constexpr int T_E     = 16;
static constexpr int NTILE   = E_EDGES / T_E;   // 15625 exact

#define SQ3f  1.7320508075688772f
#define SQ5f  2.2360679774997896f
#define SQ15f 3.8729833462074170f
#define HSQ3f 0.8660254037844386f

// ---- smem map ----
// Wh: f16[192][72] (27648 B), Wl: +27648  (block-shared)
// 8 pair regions (stride 22016):
//   [0:2304)      invH f16[16][72]
//   [2304:4608)   invL
//   [4608:17408)  wS f32[16][200]
//   [17408:22016) stage: 2 x 2304 B TMA slots
static constexpr int OFF_WL   = 27648;
static constexpr int OFF_PAIR = 55296;
static constexpr int P_STRIDE = 22016;
static constexpr int R_INVL   = 2304;
static constexpr int R_WS     = 4608;
static constexpr int R_STG    = 17408;
static constexpr int STG_SLOT = 2304;
static constexpr int SMEM_BYTES = OFF_PAIR + 8 * P_STRIDE;   // 231424

__device__ __forceinline__ uint32_t smem_u32(const void* p) {
    uint32_t a;
    asm("{ .reg .u64 t; cvta.to.shared.u64 t, %1; cvt.u32.u64 %0, t; }" : "=r"(a) : "l"(p));
    return a;
}
__device__ __forceinline__ void mma16816(float& c0, float& c1, float& c2, float& c3,
                                         uint32_t a0, uint32_t a1, uint32_t a2, uint32_t a3,
                                         uint32_t b0, uint32_t b1) {
    asm volatile("mma.sync.aligned.m16n8k16.row.col.f32.f16.f16.f32 "
                 "{%0,%1,%2,%3}, {%4,%5,%6,%7}, {%8,%9}, {%0,%1,%2,%3};"
                 : "+f"(c0), "+f"(c1), "+f"(c2), "+f"(c3)
                 : "r"(a0), "r"(a1), "r"(a2), "r"(a3), "r"(b0), "r"(b1));
}
__device__ __forceinline__ void pair_bar(int id) {
    asm volatile("bar.sync %0, 64;" :: "r"(id) : "memory");
}

__global__ void __launch_bounds__(512, 1)
sh_embed_ws(const float* __restrict__ edge_vec, const float* __restrict__ inv_g,
            const float* __restrict__ Wg, float* __restrict__ out)
{
    extern __shared__ char smem[];
    const int tid = threadIdx.x, lane = tid & 31, wid = tid >> 5;
    const int pairI = wid >> 1;                 // 0..7
    const bool isG  = (wid & 1) == 0;
    const int barid = 8 + pairI;                // named barriers 8..15

    uint32_t* WhW = (uint32_t*)smem;            // word view, row stride 36 words
    uint32_t* WlW = (uint32_t*)(smem + OFF_WL);

    char* preg = smem + OFF_PAIR + pairI * P_STRIDE;
    uint32_t* invH = (uint32_t*)preg;
    uint32_t* invL = (uint32_t*)(preg + R_INVL);
    float*    wS   = (float*)(preg + R_WS);     // f32[16][200]
    char*     stg  = preg + R_STG;
    const uint32_t stgAddr = smem_u32(stg);

    // ---- one-time: W -> f16 hi/lo tiles [col(192)][k(64)], rows padded to 72 f16 ----
    for (int u = tid; u < 192 * 64; u += 512) {
        int col = u >> 6, d = u & 63;
        float v = Wg[d * 192 + col];
        __half h = __float2half_rn(v);
        __half l = __float2half_rn(v - __half2float(h));
        *(__half*)(smem + col * 144 + d * 2)          = h;
        *(__half*)(smem + OFF_WL + col * 144 + d * 2) = l;
    }
    __syncthreads();

    const int g = lane >> 2, t = lane & 3;      // mma quad coords
    const int streams = gridDim.x * 8;

    if (isG) {
        // ================= GEMM warp =================
        #pragma unroll 1
        for (int tile = blockIdx.x * 8 + pairI; tile < NTILE; tile += streams) {
            const int eBase = tile * T_E;

            // ---- stage inv tile as f16 hi/lo (rows padded to 72 f16) ----
            {
                const float4* src = (const float4*)(inv_g + (size_t)eBase * 64);
                #pragma unroll
                for (int r = 0; r < 8; r++) {
                    int f = r * 32 + lane, e = f >> 4, i4 = f & 15;
                    float4 q = src[f];
                    __half2 h01 = __floats2half2_rn(q.x, q.y), h23 = __floats2half2_rn(q.z, q.w);
                    float2 g01 = __half22float2(h01), g23 = __half22float2(h23);
                    __half2 l01 = __floats2half2_rn(q.x - g01.x, q.y - g01.y);
                    __half2 l23 = __floats2half2_rn(q.z - g23.x, q.w - g23.y);
                    ((uint2*)invH)[e * 18 + i4] = make_uint2(*(uint32_t*)&h01, *(uint32_t*)&h23);
                    ((uint2*)invL)[e * 18 + i4] = make_uint2(*(uint32_t*)&l01, *(uint32_t*)&l23);
                }
            }
            __syncwarp();

            // ---- A fragments (4 k-chunks, hi+lo) ----
            uint32_t Ah[16], Al[16];
            #pragma unroll
            for (int kc = 0; kc < 4; kc++) {
                int b = kc * 8 + t;
                Ah[kc*4+0] = invH[g * 36 + b];      Ah[kc*4+1] = invH[(g + 8) * 36 + b];
                Ah[kc*4+2] = invH[g * 36 + b + 4];  Ah[kc*4+3] = invH[(g + 8) * 36 + b + 4];
                Al[kc*4+0] = invL[g * 36 + b];      Al[kc*4+1] = invL[(g + 8) * 36 + b];
                Al[kc*4+2] = invL[g * 36 + b + 4];  Al[kc*4+3] = invL[(g + 8) * 36 + b + 4];
            }

            pair_bar(barid);    // SYNC1: E finished reading wS of previous tile

            // ---- GEMM: 24 n-chunks in pairs, 3-term f16 split ----
            #pragma unroll 1
            for (int np = 0; np < 12; np++) {
                int n0 = np * 16, n1 = n0 + 8;
                float c0 = 0.f, c1 = 0.f, c2 = 0.f, c3 = 0.f;
                float d0 = 0.f, d1 = 0.f, d2 = 0.f, d3 = 0.f;
                #pragma unroll
                for (int kc = 0; kc < 4; kc++) {
                    int bi0 = (n0 + g) * 36 + kc * 8 + t;
                    int bi1 = (n1 + g) * 36 + kc * 8 + t;
                    uint32_t bh0 = WhW[bi0], bh1 = WhW[bi0 + 4];
                    uint32_t bl0 = WlW[bi0], bl1 = WlW[bi0 + 4];
                    uint32_t ch0 = WhW[bi1], ch1 = WhW[bi1 + 4];
                    uint32_t cl0 = WlW[bi1], cl1 = WlW[bi1 + 4];
                    const uint32_t* ah = Ah + kc * 4;
                    const uint32_t* al = Al + kc * 4;
                    mma16816(c0,c1,c2,c3, ah[0],ah[1],ah[2],ah[3], bh0,bh1);
                    mma16816(d0,d1,d2,d3, ah[0],ah[1],ah[2],ah[3], ch0,ch1);
                    mma16816(c0,c1,c2,c3, al[0],al[1],al[2],al[3], bh0,bh1);
                    mma16816(d0,d1,d2,d3, al[0],al[1],al[2],al[3], ch0,ch1);
                    mma16816(c0,c1,c2,c3, ah[0],ah[1],ah[2],ah[3], bl0,bl1);
                    mma16816(d0,d1,d2,d3, ah[0],ah[1],ah[2],ah[3], cl0,cl1);
                }
                *(float2*)(wS + g * 200 + n0 + 2 * t)       = make_float2(c0, c1);
                *(float2*)(wS + (g + 8) * 200 + n0 + 2 * t) = make_float2(c2, c3);
                *(float2*)(wS + g * 200 + n1 + 2 * t)       = make_float2(d0, d1);
                *(float2*)(wS + (g + 8) * 200 + n1 + 2 * t) = make_float2(d2, d3);
            }

            pair_bar(barid);    // SYNC2: wS ready for E
        }
    } else {
        // ================= Epilogue warp =================
        const int rot = lane >> 4;
        #pragma unroll 1
        for (int tile = blockIdx.x * 8 + pairI; tile < NTILE; tile += streams) {
            const int eBase = tile * T_E;

            pair_bar(barid);    // SYNC1: done with previous wS
            pair_bar(barid);    // SYNC2: wS(t) ready

            // prefetch edge 0's vector (warp-uniform)
            const float* vp = edge_vec + (size_t)eBase * 3;
            float vx = vp[0], vy = vp[1], vz = vp[2];

            #pragma unroll 1
            for (int e = 0; e < T_E; ++e) {
                if (lane == 0) asm volatile("cp.async.bulk.wait_group 1;" ::: "memory");
                __syncwarp();

                // SH for this edge (all lanes redundant, cheap)
                float rn = rsqrtf(vx * vx + vy * vy + vz * vz);
                float x = vx * rn, y = vy * rn, z = vz * rn;
                float sh1 = SQ3f * x, sh2 = SQ3f * y, sh3 = SQ3f * z;
                float sh4 = SQ15f * x * z;
                float sh5 = SQ15f * x * y;
                float sh6 = SQ5f  * (y * y - 0.5f * (x * x + z * z));
                float sh7 = SQ15f * y * z;
                float sh8 = (HSQ3f * SQ5f) * (z * z - x * x);

                // prefetch next edge's vector
                if (e + 1 < T_E) {
                    const float* vq = edge_vec + (size_t)(eBase + e + 1) * 3;
                    vx = vq[0]; vy = vq[1]; vz = vq[2];
                }

                const float2* wrow = (const float2*)(wS + e * 200) + lane * 3;
                float2 f0 = wrow[0], f1 = wrow[1], f2 = wrow[2];
                float w0x = f0.x, w1x = f0.y, w2x = f1.x;
                float w0y = f1.y, w1y = f2.x, w2y = f2.y;

                float2 pr[9];
                pr[0] = make_float2(w0x,         sh1 * w1x);
                pr[1] = make_float2(sh2 * w1x,   sh3 * w1x);
                pr[2] = make_float2(sh4 * w2x,   sh5 * w2x);
                pr[3] = make_float2(sh6 * w2x,   sh7 * w2x);
                pr[4] = make_float2(sh8 * w2x,   w0y);
                pr[5] = make_float2(sh1 * w1y,   sh2 * w1y);
                pr[6] = make_float2(sh3 * w1y,   sh4 * w2y);
                pr[7] = make_float2(sh5 * w2y,   sh6 * w2y);
                pr[8] = make_float2(sh7 * w2y,   sh8 * w2y);

                float2* sp = (float2*)(stg + (e & 1) * STG_SLOT) + lane * 9;
                #pragma unroll
                for (int m = 0; m < 9; m++) {
                    const int k = (m + 1) % 9;
                    float2 v = rot ? pr[k] : pr[m];
                    int    o = rot ? k     : m;
                    sp[o] = v;
                }
                __syncwarp();

                if (lane == 0) {
                    asm volatile("fence.proxy.async.shared::cta;" ::: "memory");
                    asm volatile("cp.async.bulk.global.shared::cta.bulk_group [%0], [%1], %2;"
                                 :: "l"(out + (size_t)(eBase + e) * 576),
                                    "r"(stgAddr + (uint32_t)((e & 1) * STG_SLOT)),
                                    "n"(STG_SLOT) : "memory");
                    asm volatile("cp.async.bulk.commit_group;" ::: "memory");
                }
            }
        }
        if (lane == 0) asm volatile("cp.async.bulk.wait_group 0;" ::: "memory");
        __syncwarp();
    }
}

extern "C" void kernel_launch(void* const* d_in, const int* in_sizes, int n_in,
                              void* d_out, int out_size) {
    const float* edge_vec = (const float*)d_in[0];   // [E, 3]
    const float* inv      = (const float*)d_in[1];   // [E, 64]
    const float* W        = (const float*)d_in[2];   // [64, 192]
    float* out            = (float*)d_out;           // [E, 64, 9]
    (void)in_sizes; (void)n_in; (void)out_size;

    int sms = 148;
    cudaDeviceGetAttribute(&sms, cudaDevAttrMultiProcessorCount, 0);
    cudaFuncSetAttribute(sh_embed_ws,
                         cudaFuncAttributeMaxDynamicSharedMemorySize, SMEM_BYTES);
    // 512 threads = 8 (GEMM, epilogue) warp-pairs per SM, 1 CTA/SM persistent
    sh_embed_ws<<<sms, 512, SMEM_BYTES>>>(edge_vec, inv, W, out);
}

// round 12
// speedup vs baseline: 1.1063x; 1.1063x over previous
#include <cuda_runtime.h>
#include <cuda_fp16.h>
#include <cstdint>

static constexpr int E_EDGES = 250000;
static constexpr int T_E     = 16;
static constexpr int NTILE   = E_EDGES / T_E;   // 15625 exact

#define SQ3f  1.7320508075688772f
#define SQ5f  2.2360679774997896f
#define SQ15f 3.8729833462074170f
#define HSQ3f 0.8660254037844386f

// ---- smem map ----
// Wh: f16[192][72] (27648 B), Wl: +27648  (block-shared)
// 16 warp regions (stride 11008):
//   [0:6400)   union: invH f16[16][72] @0, invL @2304  |  wS f32[8][200]
//   [6400:11008) stage: 2 x 2304 B TMA slots
static constexpr int OFF_WL   = 27648;
static constexpr int OFF_WARP = 55296;
static constexpr int P_STRIDE = 11008;
static constexpr int R_INVL   = 2304;
static constexpr int R_STG    = 6400;
static constexpr int STG_SLOT = 2304;
static constexpr int SMEM_BYTES = OFF_WARP + 16 * P_STRIDE;   // 231424

__device__ __forceinline__ uint32_t smem_u32(const void* p) {
    uint32_t a;
    asm("{ .reg .u64 t; cvta.to.shared.u64 t, %1; cvt.u32.u64 %0, t; }" : "=r"(a) : "l"(p));
    return a;
}
__device__ __forceinline__ void mma16816(float& c0, float& c1, float& c2, float& c3,
                                         uint32_t a0, uint32_t a1, uint32_t a2, uint32_t a3,
                                         uint32_t b0, uint32_t b1) {
    asm volatile("mma.sync.aligned.m16n8k16.row.col.f32.f16.f16.f32 "
                 "{%0,%1,%2,%3}, {%4,%5,%6,%7}, {%8,%9}, {%0,%1,%2,%3};"
                 : "+f"(c0), "+f"(c1), "+f"(c2), "+f"(c3)
                 : "r"(a0), "r"(a1), "r"(a2), "r"(a3), "r"(b0), "r"(b1));
}

__global__ void __launch_bounds__(512, 1)
sh_embed_hmma16(const float* __restrict__ edge_vec, const float* __restrict__ inv_g,
                const float* __restrict__ Wg, float* __restrict__ out)
{
    extern __shared__ char smem[];
    const int tid = threadIdx.x, lane = tid & 31, wid = tid >> 5;
    const int g = lane >> 2, t = lane & 3;     // mma quad coords

    uint32_t* WhW = (uint32_t*)smem;           // word view, row stride 36 words
    uint32_t* WlW = (uint32_t*)(smem + OFF_WL);

    char* wr = smem + OFF_WARP + wid * P_STRIDE;
    uint32_t* invH = (uint32_t*)wr;            // f16[16][72] (dead after frag load)
    uint32_t* invL = (uint32_t*)(wr + R_INVL);
    float*    wS   = (float*)wr;               // f32[8][200] (aliases inv region)
    char*     stg  = wr + R_STG;
    const uint32_t stgAddr = smem_u32(stg);

    // ---- one-time: W -> f16 hi/lo tiles [col(192)][k(64)], rows padded to 72 f16 ----
    for (int u = tid; u < 192 * 64; u += 512) {
        int col = u >> 6, d = u & 63;
        float v = Wg[d * 192 + col];
        __half h = __float2half_rn(v);
        __half l = __float2half_rn(v - __half2float(h));
        *(__half*)(smem + col * 144 + d * 2)          = h;
        *(__half*)(smem + OFF_WL + col * 144 + d * 2) = l;
    }
    __syncthreads();

    const int rot = lane >> 4;
    const int streams = gridDim.x * 16;
    #pragma unroll 1
    for (int tile = blockIdx.x * 16 + wid; tile < NTILE; tile += streams) {
        const int eBase = tile * T_E;
        __syncwarp();   // previous tile's wS reads done before overwriting (alias)

        // ---- stage inv tile as f16 hi/lo (rows padded to 72 f16) ----
        {
            const float4* src = (const float4*)(inv_g + (size_t)eBase * 64);
            #pragma unroll
            for (int r = 0; r < 8; r++) {
                int f = r * 32 + lane, e = f >> 4, i4 = f & 15;
                float4 q = src[f];
                __half2 h01 = __floats2half2_rn(q.x, q.y), h23 = __floats2half2_rn(q.z, q.w);
                float2 g01 = __half22float2(h01), g23 = __half22float2(h23);
                __half2 l01 = __floats2half2_rn(q.x - g01.x, q.y - g01.y);
                __half2 l23 = __floats2half2_rn(q.z - g23.x, q.w - g23.y);
                ((uint2*)invH)[e * 18 + i4] = make_uint2(*(uint32_t*)&h01, *(uint32_t*)&h23);
                ((uint2*)invL)[e * 18 + i4] = make_uint2(*(uint32_t*)&l01, *(uint32_t*)&l23);
            }
        }
        __syncwarp();

        // ---- A fragments (4 k-chunks, hi+lo) into registers ----
        uint32_t Ah[16], Al[16];
        #pragma unroll
        for (int kc = 0; kc < 4; kc++) {
            int b = kc * 8 + t;
            Ah[kc*4+0] = invH[g * 36 + b];      Ah[kc*4+1] = invH[(g + 8) * 36 + b];
            Ah[kc*4+2] = invH[g * 36 + b + 4];  Ah[kc*4+3] = invH[(g + 8) * 36 + b + 4];
            Al[kc*4+0] = invL[g * 36 + b];      Al[kc*4+1] = invL[(g + 8) * 36 + b];
            Al[kc*4+2] = invL[g * 36 + b + 4];  Al[kc*4+3] = invL[(g + 8) * 36 + b + 4];
        }
        __syncwarp();   // frag reads done before wS (alias) is written

        // ---- GEMM: 24 n-chunks in pairs; rows 0-7 -> wS, rows 8-15 held in regs ----
        float cH[48];
        #pragma unroll 1
        for (int np = 0; np < 12; np++) {
            int n0 = np * 16, n1 = n0 + 8;
            float c0 = 0.f, c1 = 0.f, c2 = 0.f, c3 = 0.f;
            float d0 = 0.f, d1 = 0.f, d2 = 0.f, d3 = 0.f;
            #pragma unroll
            for (int kc = 0; kc < 4; kc++) {
                int bi0 = (n0 + g) * 36 + kc * 8 + t;
                int bi1 = (n1 + g) * 36 + kc * 8 + t;
                uint32_t bh0 = WhW[bi0], bh1 = WhW[bi0 + 4];
                uint32_t bl0 = WlW[bi0], bl1 = WlW[bi0 + 4];
                uint32_t ch0 = WhW[bi1], ch1 = WhW[bi1 + 4];
                uint32_t cl0 = WlW[bi1], cl1 = WlW[bi1 + 4];
                const uint32_t* ah = Ah + kc * 4;
                const uint32_t* al = Al + kc * 4;
                mma16816(c0,c1,c2,c3, ah[0],ah[1],ah[2],ah[3], bh0,bh1);
                mma16816(d0,d1,d2,d3, ah[0],ah[1],ah[2],ah[3], ch0,ch1);
                mma16816(c0,c1,c2,c3, al[0],al[1],al[2],al[3], bh0,bh1);
                mma16816(d0,d1,d2,d3, al[0],al[1],al[2],al[3], ch0,ch1);
                mma16816(c0,c1,c2,c3, ah[0],ah[1],ah[2],ah[3], bl0,bl1);
                mma16816(d0,d1,d2,d3, ah[0],ah[1],ah[2],ah[3], cl0,cl1);
            }
            *(float2*)(wS + g * 200 + n0 + 2 * t) = make_float2(c0, c1);
            *(float2*)(wS + g * 200 + n1 + 2 * t) = make_float2(d0, d1);
            cH[np*4+0] = c2; cH[np*4+1] = c3;     // edges 8-15, n-chunk n0
            cH[np*4+2] = d2; cH[np*4+3] = d3;     // edges 8-15, n-chunk n1
        }
        __syncwarp();

        // ---- two epilogue phases: edges 0-7 from wS, then 8-15 from held regs ----
        #pragma unroll 1
        for (int phI = 0; phI < 2; phI++) {
            if (phI == 1) {
                __syncwarp();   // phase-0 wS reads done before overwrite
                #pragma unroll
                for (int np = 0; np < 12; np++) {
                    *(float2*)(wS + g * 200 + np * 16 + 2 * t)
                        = make_float2(cH[np*4+0], cH[np*4+1]);
                    *(float2*)(wS + g * 200 + np * 16 + 8 + 2 * t)
                        = make_float2(cH[np*4+2], cH[np*4+3]);
                }
                __syncwarp();
            }
            const int eOff = eBase + phI * 8;

            #pragma unroll 1
            for (int e = 0; e < 8; ++e) {
                if (lane == 0) asm volatile("cp.async.bulk.wait_group 1;" ::: "memory");
                __syncwarp();

                // SH for this edge (warp-uniform read, redundant compute)
                const float* vp = edge_vec + (size_t)(eOff + e) * 3;
                float vx = vp[0], vy = vp[1], vz = vp[2];
                float rn = rsqrtf(vx * vx + vy * vy + vz * vz);
                float x = vx * rn, y = vy * rn, z = vz * rn;
                float sh1 = SQ3f * x, sh2 = SQ3f * y, sh3 = SQ3f * z;
                float sh4 = SQ15f * x * z;
                float sh5 = SQ15f * x * y;
                float sh6 = SQ5f  * (y * y - 0.5f * (x * x + z * z));
                float sh7 = SQ15f * y * z;
                float sh8 = (HSQ3f * SQ5f) * (z * z - x * x);

                const float2* wrow = (const float2*)(wS + e * 200) + lane * 3;
                float2 f0 = wrow[0], f1 = wrow[1], f2 = wrow[2];
                float w0x = f0.x, w1x = f0.y, w2x = f1.x;
                float w0y = f1.y, w1y = f2.x, w2y = f2.y;

                float2 pr[9];
                pr[0] = make_float2(w0x,         sh1 * w1x);
                pr[1] = make_float2(sh2 * w1x,   sh3 * w1x);
                pr[2] = make_float2(sh4 * w2x,   sh5 * w2x);
                pr[3] = make_float2(sh6 * w2x,   sh7 * w2x);
                pr[4] = make_float2(sh8 * w2x,   w0y);
                pr[5] = make_float2(sh1 * w1y,   sh2 * w1y);
                pr[6] = make_float2(sh3 * w1y,   sh4 * w2y);
                pr[7] = make_float2(sh5 * w2y,   sh6 * w2y);
                pr[8] = make_float2(sh7 * w2y,   sh8 * w2y);

                float2* sp = (float2*)(stg + (e & 1) * STG_SLOT) + lane * 9;
                #pragma unroll
                for (int m = 0; m < 9; m++) {
                    const int k = (m + 1) % 9;
                    float2 v = rot ? pr[k] : pr[m];
                    int    o = rot ? k     : m;
                    sp[o] = v;
                }
                __syncwarp();

                if (lane == 0) {
                    asm volatile("fence.proxy.async.shared::cta;" ::: "memory");
                    asm volatile("cp.async.bulk.global.shared::cta.bulk_group [%0], [%1], %2;"
                                 :: "l"(out + (size_t)(eOff + e) * 576),
                                    "r"(stgAddr + (uint32_t)((e & 1) * STG_SLOT)),
                                    "n"(STG_SLOT) : "memory");
                    asm volatile("cp.async.bulk.commit_group;" ::: "memory");
                }
            }
        }
    }

    if (lane == 0) asm volatile("cp.async.bulk.wait_group 0;" ::: "memory");
    __syncwarp();
}

extern "C" void kernel_launch(void* const* d_in, const int* in_sizes, int n_in,
                              void* d_out, int out_size) {
    const float* edge_vec = (const float*)d_in[0];   // [E, 3]
    const float* inv      = (const float*)d_in[1];   // [E, 64]
    const float* W        = (const float*)d_in[2];   // [64, 192]
    float* out            = (float*)d_out;           // [E, 64, 9]
    (void)in_sizes; (void)n_in; (void)out_size;

    int sms = 148;
    cudaDeviceGetAttribute(&sms, cudaDevAttrMultiProcessorCount, 0);
    cudaFuncSetAttribute(sh_embed_hmma16,
                         cudaFuncAttributeMaxDynamicSharedMemorySize, SMEM_BYTES);
    // 512 threads = 16 independent warp streams per SM, 1 CTA/SM persistent
    sh_embed_hmma16<<<sms, 512, SMEM_BYTES>>>(edge_vec, inv, W, out);
}

// round 13
// speedup vs baseline: 1.1961x; 1.0812x over previous
#include <cuda_runtime.h>
#include <cuda_fp16.h>
#include <cstdint>

static constexpr int E_EDGES = 250000;
static constexpr int T_E     = 16;
static constexpr int NTILE   = E_EDGES / T_E;   // 15625 exact

#define SQ3f  1.7320508075688772f
#define SQ5f  2.2360679774997896f
#define SQ15f 3.8729833462074170f
#define HSQ3f 0.8660254037844386f

// ---- smem map ----
// Wh: f16[192][72] (27648 B), Wl: +27648  (block-shared)
// 8 warp regions (stride 22016):
//   [0:12800)     wS f32[16][200]  (ALIASES invH f16[16][72] @0 + invL @2304)
//   [12800:22016) stage: 2 slots x 4608 B (one 2-edge pair each)
static constexpr int OFF_WL   = 27648;
static constexpr int OFF_WARP = 55296;
static constexpr int P_STRIDE = 22016;
static constexpr int R_INVL   = 2304;
static constexpr int R_STG    = 12800;
static constexpr int PAIR_B   = 4608;
static constexpr int SMEM_BYTES = OFF_WARP + 8 * P_STRIDE;   // 231424

__device__ __forceinline__ uint32_t smem_u32(const void* p) {
    uint32_t a;
    asm("{ .reg .u64 t; cvta.to.shared.u64 t, %1; cvt.u32.u64 %0, t; }" : "=r"(a) : "l"(p));
    return a;
}
__device__ __forceinline__ void mma16816(float& c0, float& c1, float& c2, float& c3,
                                         uint32_t a0, uint32_t a1, uint32_t a2, uint32_t a3,
                                         uint32_t b0, uint32_t b1) {
    asm volatile("mma.sync.aligned.m16n8k16.row.col.f32.f16.f16.f32 "
                 "{%0,%1,%2,%3}, {%4,%5,%6,%7}, {%8,%9}, {%0,%1,%2,%3};"
                 : "+f"(c0), "+f"(c1), "+f"(c2), "+f"(c3)
                 : "r"(a0), "r"(a1), "r"(a2), "r"(a3), "r"(b0), "r"(b1));
}

__global__ void __launch_bounds__(256, 1)
sh_embed_hmma_p(const float* __restrict__ edge_vec, const float* __restrict__ inv_g,
                const float* __restrict__ Wg, float* __restrict__ out)
{
    extern __shared__ char smem[];
    const int tid = threadIdx.x, lane = tid & 31, wid = tid >> 5;
    const int g = lane >> 2, t = lane & 3;     // mma quad coords

    uint32_t* WhW = (uint32_t*)smem;           // word view, row stride 36 words
    uint32_t* WlW = (uint32_t*)(smem + OFF_WL);

    char* wr = smem + OFF_WARP + wid * P_STRIDE;
    uint32_t* invH = (uint32_t*)wr;            // f16[16][72] (dead after frag load)
    uint32_t* invL = (uint32_t*)(wr + R_INVL);
    float*    wS   = (float*)wr;               // f32[16][200] (aliases inv region)
    char*     stg  = wr + R_STG;
    const uint32_t stgAddr = smem_u32(stg);

    // ---- one-time: W -> f16 hi/lo tiles [col(192)][k(64)], rows padded to 72 f16 ----
    for (int u = tid; u < 192 * 64; u += 256) {
        int col = u >> 6, d = u & 63;
        float v = Wg[d * 192 + col];
        __half h = __float2half_rn(v);
        __half l = __float2half_rn(v - __half2float(h));
        *(__half*)(smem + col * 144 + d * 2)          = h;
        *(__half*)(smem + OFF_WL + col * 144 + d * 2) = l;
    }
    __syncthreads();

    const int half = lane >> 4;                // epilogue: edge within pair
    const int cg   = lane & 15;                // epilogue: 4-channel group
    const int streams = gridDim.x * 8;
    #pragma unroll 1
    for (int tile = blockIdx.x * 8 + wid; tile < NTILE; tile += streams) {
        const int eBase = tile * T_E;
        __syncwarp();   // previous tile's wS reads done before overwriting (alias)

        // ---- stage inv tile as f16 hi/lo (rows padded to 72 f16) ----
        {
            const float4* src = (const float4*)(inv_g + (size_t)eBase * 64);
            #pragma unroll
            for (int r = 0; r < 8; r++) {
                int f = r * 32 + lane, e = f >> 4, i4 = f & 15;
                float4 q = src[f];
                __half2 h01 = __floats2half2_rn(q.x, q.y), h23 = __floats2half2_rn(q.z, q.w);
                float2 g01 = __half22float2(h01), g23 = __half22float2(h23);
                __half2 l01 = __floats2half2_rn(q.x - g01.x, q.y - g01.y);
                __half2 l23 = __floats2half2_rn(q.z - g23.x, q.w - g23.y);
                ((uint2*)invH)[e * 18 + i4] = make_uint2(*(uint32_t*)&h01, *(uint32_t*)&h23);
                ((uint2*)invL)[e * 18 + i4] = make_uint2(*(uint32_t*)&l01, *(uint32_t*)&l23);
            }
        }
        __syncwarp();

        // ---- A fragments (4 k-chunks, hi+lo) into registers ----
        uint32_t Ah[16], Al[16];
        #pragma unroll
        for (int kc = 0; kc < 4; kc++) {
            int b = kc * 8 + t;
            Ah[kc*4+0] = invH[g * 36 + b];      Ah[kc*4+1] = invH[(g + 8) * 36 + b];
            Ah[kc*4+2] = invH[g * 36 + b + 4];  Ah[kc*4+3] = invH[(g + 8) * 36 + b + 4];
            Al[kc*4+0] = invL[g * 36 + b];      Al[kc*4+1] = invL[(g + 8) * 36 + b];
            Al[kc*4+2] = invL[g * 36 + b + 4];  Al[kc*4+3] = invL[(g + 8) * 36 + b + 4];
        }
        __syncwarp();   // frag reads done before wS (alias) is written

        // ---- GEMM: 24 n-chunks in pairs, 3-term f16 split; all 16 rows -> wS ----
        #pragma unroll 1
        for (int np = 0; np < 12; np++) {
            int n0 = np * 16, n1 = n0 + 8;
            float c0 = 0.f, c1 = 0.f, c2 = 0.f, c3 = 0.f;
            float d0 = 0.f, d1 = 0.f, d2 = 0.f, d3 = 0.f;
            #pragma unroll
            for (int kc = 0; kc < 4; kc++) {
                int bi0 = (n0 + g) * 36 + kc * 8 + t;
                int bi1 = (n1 + g) * 36 + kc * 8 + t;
                uint32_t bh0 = WhW[bi0], bh1 = WhW[bi0 + 4];
                uint32_t bl0 = WlW[bi0], bl1 = WlW[bi0 + 4];
                uint32_t ch0 = WhW[bi1], ch1 = WhW[bi1 + 4];
                uint32_t cl0 = WlW[bi1], cl1 = WlW[bi1 + 4];
                const uint32_t* ah = Ah + kc * 4;
                const uint32_t* al = Al + kc * 4;
                mma16816(c0,c1,c2,c3, ah[0],ah[1],ah[2],ah[3], bh0,bh1);
                mma16816(d0,d1,d2,d3, ah[0],ah[1],ah[2],ah[3], ch0,ch1);
                mma16816(c0,c1,c2,c3, al[0],al[1],al[2],al[3], bh0,bh1);
                mma16816(d0,d1,d2,d3, al[0],al[1],al[2],al[3], ch0,ch1);
                mma16816(c0,c1,c2,c3, ah[0],ah[1],ah[2],ah[3], bl0,bl1);
                mma16816(d0,d1,d2,d3, ah[0],ah[1],ah[2],ah[3], cl0,cl1);
            }
            *(float2*)(wS + g * 200 + n0 + 2 * t)       = make_float2(c0, c1);
            *(float2*)(wS + (g + 8) * 200 + n0 + 2 * t) = make_float2(c2, c3);
            *(float2*)(wS + g * 200 + n1 + 2 * t)       = make_float2(d0, d1);
            *(float2*)(wS + (g + 8) * 200 + n1 + 2 * t) = make_float2(d2, d3);
        }
        __syncwarp();   // wS visible to all lanes

        // ---- epilogue: 8 passes of 2 edges; lane = (edge-half, 4-channel group) ----
        #pragma unroll 1
        for (int ep = 0; ep < 8; ++ep) {
            const int eRow = 2 * ep + half;
            // hoist edge_vec load above the slot wait
            const float* vp = edge_vec + (size_t)(eBase + eRow) * 3;
            float vx = vp[0], vy = vp[1], vz = vp[2];

            if (lane == 0) asm volatile("cp.async.bulk.wait_group 1;" ::: "memory");
            __syncwarp();

            float rn = rsqrtf(vx * vx + vy * vy + vz * vz);
            float x = vx * rn, y = vy * rn, z = vz * rn;
            float sh1 = SQ3f * x, sh2 = SQ3f * y, sh3 = SQ3f * z;
            float sh4 = SQ15f * x * z;
            float sh5 = SQ15f * x * y;
            float sh6 = SQ5f  * (y * y - 0.5f * (x * x + z * z));
            float sh7 = SQ15f * y * z;
            float sh8 = (HSQ3f * SQ5f) * (z * z - x * x);

            // 12 contiguous w floats = channels 4cg..4cg+3 (w0,w1,w2 triplets)
            const float4* wv = (const float4*)(wS + eRow * 200 + cg * 12);
            float4 wa = wv[0], wb = wv[1], wc = wv[2];

            float4* sp = (float4*)(stg + (ep & 1) * PAIR_B + (size_t)lane * 144);
            sp[0] = make_float4(wa.x,       sh1 * wa.y, sh2 * wa.y, sh3 * wa.y);
            sp[1] = make_float4(sh4 * wa.z, sh5 * wa.z, sh6 * wa.z, sh7 * wa.z);
            sp[2] = make_float4(sh8 * wa.z, wa.w,       sh1 * wb.x, sh2 * wb.x);
            sp[3] = make_float4(sh3 * wb.x, sh4 * wb.y, sh5 * wb.y, sh6 * wb.y);
            sp[4] = make_float4(sh7 * wb.y, sh8 * wb.y, wb.z,       sh1 * wb.w);
            sp[5] = make_float4(sh2 * wb.w, sh3 * wb.w, sh4 * wc.x, sh5 * wc.x);
            sp[6] = make_float4(sh6 * wc.x, sh7 * wc.x, sh8 * wc.x, wc.y);
            sp[7] = make_float4(sh1 * wc.z, sh2 * wc.z, sh3 * wc.z, sh4 * wc.w);
            sp[8] = make_float4(sh5 * wc.w, sh6 * wc.w, sh7 * wc.w, sh8 * wc.w);
            __syncwarp();

            if (lane == 0) {
                asm volatile("fence.proxy.async.shared::cta;" ::: "memory");
                asm volatile("cp.async.bulk.global.shared::cta.bulk_group [%0], [%1], %2;"
                             :: "l"(out + (size_t)(eBase + 2 * ep) * 576),
                                "r"(stgAddr + (uint32_t)((ep & 1) * PAIR_B)),
                                "n"(PAIR_B) : "memory");
                asm volatile("cp.async.bulk.commit_group;" ::: "memory");
            }
        }
    }

    if (lane == 0) asm volatile("cp.async.bulk.wait_group 0;" ::: "memory");
    __syncwarp();
}

extern "C" void kernel_launch(void* const* d_in, const int* in_sizes, int n_in,
                              void* d_out, int out_size) {
    const float* edge_vec = (const float*)d_in[0];   // [E, 3]
    const float* inv      = (const float*)d_in[1];   // [E, 64]
    const float* W        = (const float*)d_in[2];   // [64, 192]
    float* out            = (float*)d_out;           // [E, 64, 9]
    (void)in_sizes; (void)n_in; (void)out_size;

    int sms = 148;
    cudaDeviceGetAttribute(&sms, cudaDevAttrMultiProcessorCount, 0);
    cudaFuncSetAttribute(sh_embed_hmma_p,
                         cudaFuncAttributeMaxDynamicSharedMemorySize, SMEM_BYTES);
    // 256 threads = 8 independent warp streams per SM, 1 CTA/SM persistent
    sh_embed_hmma_p<<<sms, 256, SMEM_BYTES>>>(edge_vec, inv, W, out);
}